// round 17
// baseline (speedup 1.0000x reference)
#include <cuda_runtime.h>
#include <cuda_fp16.h>
#include <cstdint>

#define N_NODES 100000
#define D 64
#define E_MAX 1700000
#define SCAN_BLK 512
#define KSTRIDE 68  // floats per k-row in smem; 68*4=272B, 16B-aligned

// Scratch (__device__ globals: the sanctioned allocation-free path).
__device__ __align__(16) __half g_h[N_NODES * D];    // g = (x @ W^T) * dinv[row], fp16
__device__ __align__(16) float h1_buf[N_NODES * D];  // layer-1 output (fp32)
__device__ float dinv_buf[N_NODES];
__device__ int cnt_buf[N_NODES];       // in-degree histogram (re-zeroed by scan_finish)
__device__ int row_start[N_NODES + 1]; // CSR row offsets (by dst)
__device__ int cursor_buf[N_NODES];    // placement cursors
__device__ int csr_src[E_MAX];         // CSR column (src) indices
__device__ int block_sums[(N_NODES + SCAN_BLK - 1) / SCAN_BLK];

// f32x2 packed helpers (Blackwell FFMA2 path — PTX only)
__device__ __forceinline__ void ffma2(unsigned long long& acc,
                                      unsigned long long a, unsigned long long b) {
    asm("fma.rn.f32x2 %0, %1, %2, %3;" : "=l"(acc) : "l"(a), "l"(b), "l"(acc));
}
__device__ __forceinline__ unsigned long long pack2(float lo, float hi) {
    unsigned long long r;
    asm("mov.b64 %0, {%1, %2};" : "=l"(r) : "f"(lo), "f"(hi));
    return r;
}
__device__ __forceinline__ void unpack2(unsigned long long v, float& lo, float& hi) {
    asm("mov.b64 {%0, %1}, %2;" : "=f"(lo), "=f"(hi) : "l"(v));
}

// ---------------------------------------------------------------------------
// Histogram of in-degrees. cnt_buf zero on entry (.bss call 1, re-zeroed
// by scan_finish each call). Edge buffer is int32 (proven in rounds 3/4).
// ---------------------------------------------------------------------------
__global__ void hist_kernel(const int* __restrict__ ei, int E) {
    int e = blockIdx.x * blockDim.x + threadIdx.x;
    if (e < E) atomicAdd(&cnt_buf[ei[E + e]], 1);
}

__global__ __launch_bounds__(SCAN_BLK) void scan_block_kernel() {
    __shared__ int s[SCAN_BLK];
    int i = blockIdx.x * SCAN_BLK + threadIdx.x;
    int v = (i < N_NODES) ? cnt_buf[i] : 0;
    s[threadIdx.x] = v;
    __syncthreads();
#pragma unroll
    for (int off = 1; off < SCAN_BLK; off <<= 1) {
        int t = (threadIdx.x >= off) ? s[threadIdx.x - off] : 0;
        __syncthreads();
        s[threadIdx.x] += t;
        __syncthreads();
    }
    if (i < N_NODES) row_start[i] = s[threadIdx.x] - v;
    if (threadIdx.x == SCAN_BLK - 1) block_sums[blockIdx.x] = s[threadIdx.x];
}

__global__ __launch_bounds__(256) void scan_finish_kernel(int E, int nb) {
    __shared__ int s[256];
    __shared__ int excl[256];
    int v = (threadIdx.x < nb) ? block_sums[threadIdx.x] : 0;
    s[threadIdx.x] = v;
    __syncthreads();
#pragma unroll
    for (int off = 1; off < 256; off <<= 1) {
        int t = (threadIdx.x >= off) ? s[threadIdx.x - off] : 0;
        __syncthreads();
        s[threadIdx.x] += t;
        __syncthreads();
    }
    excl[threadIdx.x] = s[threadIdx.x] - v;
    __syncthreads();

    int i = blockIdx.x * blockDim.x + threadIdx.x;
    if (i < N_NODES) {
        int r = row_start[i] + excl[i / SCAN_BLK];
        row_start[i] = r;
        cursor_buf[i] = r;
        dinv_buf[i] = rsqrtf((float)cnt_buf[i] + 1.0f);  // deg + self loop
        cnt_buf[i] = 0;
    }
    if (i == 0) row_start[N_NODES] = E;
}

__global__ void place_kernel(const int* __restrict__ ei, int E) {
    int e = blockIdx.x * blockDim.x + threadIdx.x;
    if (e < E) {
        int s = ei[e];
        int d = ei[E + e];
        int pos = atomicAdd(&cursor_buf[d], 1);
        csr_src[pos] = s;
    }
}

// ---------------------------------------------------------------------------
// GEMM: g[row] = (x[row] @ W^T) * dinv[row], stored as fp16.
// (r12 conflict-free smem layout + FFMA2 inner loop.)
// ---------------------------------------------------------------------------
__global__ __launch_bounds__(256) void gemm_scale_kernel(
    const float* __restrict__ x, const float* __restrict__ W) {
    __shared__ __align__(16) float Wt[64 * KSTRIDE];  // [k][j], swizzled
    __shared__ __align__(16) float Xt[64 * KSTRIDE];  // [k][r], swizzled

    int tid = threadIdx.x;
    int rowBase = blockIdx.x * 64;

    const float4* W4 = (const float4*)W;
    const float4* x4 = (const float4*)x;
    for (int i = tid; i < 1024; i += 256) {
        int j = i >> 4;
        int kk = i & 15;
        int j4 = j >> 2, jr = j & 3;
        float4 w = W4[i];
#pragma unroll
        for (int c = 0; c < 4; c++) {
            int k = 4 * kk + c;
            int col = ((j4 ^ (kk & 7)) << 2) + jr;
            float wv = (c == 0) ? w.x : (c == 1) ? w.y : (c == 2) ? w.z : w.w;
            Wt[k * KSTRIDE + col] = wv;
        }
        float4 xv = make_float4(0.f, 0.f, 0.f, 0.f);
        if (rowBase + j < N_NODES) xv = x4[(size_t)(rowBase + j) * 16 + kk];
#pragma unroll
        for (int c = 0; c < 4; c++) {
            int k = 4 * kk + c;
            int col = ((j4 ^ (kk & 7)) << 2) + jr;
            float vv = (c == 0) ? xv.x : (c == 1) ? xv.y : (c == 2) ? xv.z : xv.w;
            Xt[k * KSTRIDE + col] = vv;
        }
    }
    __syncthreads();

    int tx = tid & 15;
    int ty = tid >> 4;

    unsigned long long acc2[4][2];
#pragma unroll
    for (int i = 0; i < 4; i++) { acc2[i][0] = 0ULL; acc2[i][1] = 0ULL; }

#pragma unroll
    for (int k = 0; k < 64; k++) {
        int f = (k >> 2) & 7;
        const ulonglong2 wv2 =
            *(const ulonglong2*)&Wt[k * KSTRIDE + ((tx ^ f) << 2)];
        const float4 xv = *(const float4*)&Xt[k * KSTRIDE + ((ty ^ f) << 2)];
        float xr[4] = {xv.x, xv.y, xv.z, xv.w};
#pragma unroll
        for (int i = 0; i < 4; i++) {
            unsigned long long xx = pack2(xr[i], xr[i]);
            ffma2(acc2[i][0], xx, wv2.x);
            ffma2(acc2[i][1], xx, wv2.y);
        }
    }

#pragma unroll
    for (int i = 0; i < 4; i++) {
        int row = rowBase + ty * 4 + i;
        if (row < N_NODES) {
            float di = dinv_buf[row];
            float o0, o1, o2, o3;
            unpack2(acc2[i][0], o0, o1);
            unpack2(acc2[i][1], o2, o3);
            __half2 h01 = __floats2half2_rn(o0 * di, o1 * di);
            __half2 h23 = __floats2half2_rn(o2 * di, o3 * di);
            uint2 pk;
            pk.x = *(unsigned int*)&h01;
            pk.y = *(unsigned int*)&h23;
            ((uint2*)g_h)[(size_t)row * 16 + tx] = pk;
        }
    }
}

// ---------------------------------------------------------------------------
// Pull + fused finalize, fp16 gathers, fp32 accumulate. (r15 form, unchanged)
// ---------------------------------------------------------------------------
__device__ __forceinline__ void acc_row(float4& acc, uint2 pk) {
    __half2 h01 = *(__half2*)&pk.x;
    __half2 h23 = *(__half2*)&pk.y;
    float2 f01 = __half22float2(h01);
    float2 f23 = __half22float2(h23);
    acc.x += f01.x;
    acc.y += f01.y;
    acc.z += f23.x;
    acc.w += f23.y;
}

__global__ __launch_bounds__(256) void pull_kernel(
    const float* __restrict__ b, float* __restrict__ out) {
    int gid = blockIdx.x * blockDim.x + threadIdx.x;
    int node = gid >> 4;
    if (node >= N_NODES) return;
    int q = gid & 15;

    const uint2* g2 = (const uint2*)g_h;
    int beg = row_start[node];
    int end = row_start[node + 1];

    float4 acc = make_float4(0.f, 0.f, 0.f, 0.f);
    acc_row(acc, g2[(size_t)node * 16 + q]);  // self loop

    int n4 = (end - beg) & ~3;
    if (n4 > 0) {
        int s0 = csr_src[beg];
        int s1 = csr_src[beg + 1];
        int s2 = csr_src[beg + 2];
        int s3 = csr_src[beg + 3];
#pragma unroll 1
        for (int e = beg + 4; e < beg + n4; e += 4) {
            int t0 = csr_src[e];
            int t1 = csr_src[e + 1];
            int t2 = csr_src[e + 2];
            int t3 = csr_src[e + 3];
            uint2 v0 = g2[(size_t)s0 * 16 + q];
            uint2 v1 = g2[(size_t)s1 * 16 + q];
            uint2 v2 = g2[(size_t)s2 * 16 + q];
            uint2 v3 = g2[(size_t)s3 * 16 + q];
            acc_row(acc, v0);
            acc_row(acc, v1);
            acc_row(acc, v2);
            acc_row(acc, v3);
            s0 = t0; s1 = t1; s2 = t2; s3 = t3;
        }
        uint2 v0 = g2[(size_t)s0 * 16 + q];
        uint2 v1 = g2[(size_t)s1 * 16 + q];
        uint2 v2 = g2[(size_t)s2 * 16 + q];
        uint2 v3 = g2[(size_t)s3 * 16 + q];
        acc_row(acc, v0);
        acc_row(acc, v1);
        acc_row(acc, v2);
        acc_row(acc, v3);
    }
    for (int e = beg + n4; e < end; e++) {
        int s = csr_src[e];
        acc_row(acc, g2[(size_t)s * 16 + q]);
    }

    float di = dinv_buf[node];
    float4 bb = ((const float4*)b)[q];
    float4 o;
    o.x = fmaf(di, acc.x, bb.x);
    o.y = fmaf(di, acc.y, bb.y);
    o.z = fmaf(di, acc.z, bb.z);
    o.w = fmaf(di, acc.w, bb.w);
    ((float4*)out)[gid] = o;
}

// ---------------------------------------------------------------------------
extern "C" void kernel_launch(void* const* d_in, const int* in_sizes, int n_in,
                              void* d_out, int out_size) {
    const float* x = (const float*)d_in[0];
    const int* ei = (const int*)d_in[1];
    const float* W1 = (const float*)d_in[2];
    const float* b1 = (const float*)d_in[3];
    const float* W2 = (const float*)d_in[4];
    const float* b2 = (const float*)d_in[5];
    float* out = (float*)d_out;

    int E = in_sizes[1] / 2;

    int nThreads = 256;
    int nodeBlocks = (N_NODES + nThreads - 1) / nThreads;
    int edgeBlocks = (E + nThreads - 1) / nThreads;
    int gemmBlocks = (N_NODES + 63) / 64;
    int pullBlocks = (N_NODES * 16 + nThreads - 1) / nThreads;
    int scanBlocks = (N_NODES + SCAN_BLK - 1) / SCAN_BLK;

    hist_kernel<<<edgeBlocks, nThreads>>>(ei, E);                 // 1
    scan_block_kernel<<<scanBlocks, SCAN_BLK>>>();                // 2
    scan_finish_kernel<<<nodeBlocks, nThreads>>>(E, scanBlocks);  // 3

    // MEASUREMENT: full-grid duplicate pull in the ncu capture slot (#4).
    // Reads persistent state: csr/row_start from the previous call (identical
    // values every call), g_h from the previous call's layer-2 GEMM — a fully
    // realistic pull workload. Writes h1_buf, which the real pull1 below
    // overwrites -> deterministic output. Deleted next round.
    pull_kernel<<<pullBlocks, nThreads>>>(b1, h1_buf);            // 4 <-- ncu window

    gemm_scale_kernel<<<gemmBlocks, nThreads>>>(x, W1);           // 5
    place_kernel<<<edgeBlocks, nThreads>>>(ei, E);                // 6

    // Layer 1 aggregation
    pull_kernel<<<pullBlocks, nThreads>>>(b1, h1_buf);            // 7

    // Layer 2
    gemm_scale_kernel<<<gemmBlocks, nThreads>>>(h1_buf, W2);      // 8
    pull_kernel<<<pullBlocks, nThreads>>>(b2, out);               // 9
}